// round 16
// baseline (speedup 1.0000x reference)
#include <cuda_runtime.h>
#include <mma.h>
#include <math.h>

using namespace nvcuda;

#define TGT 2048
#define BSZ 4
#define E   1024
#define H   16
#define HD  64
#define M1  (TGT*BSZ)   // 8192
#define NBH (BSZ*H)     // 64

// ---- scratch (static device globals; no allocation allowed) ----
__device__ float g_q[(size_t)NBH*TGT*HD];       // [B,H,T,HD]
__device__ float g_k[(size_t)NBH*TGT*HD];
__device__ float g_v[(size_t)NBH*TGT*HD];
__device__ float g_ctx[(size_t)M1*E];           // [T,B,E]
__device__ float g_tmp[(size_t)3*M1*E];         // raw GEMM staging (100MB)
__device__ float g_m[(size_t)NBH*TGT];          // softmax row max
__device__ float g_s[(size_t)NBH*TGT];          // softmax row sum

// ============================================================
// PART 1: qkv / outproj tf32 WMMA GEMMs (validated R13/R15 path)
// ============================================================

#define NT_SMEM_BYTES  (2*128*40*2*4)

#define MMA_NT_LOOP_DB(APTR, LDA, BPTR, LDB, KTOT)                              \
    extern __shared__ float sm_[];                                              \
    float* As = sm_;                 /* [2][128][40] */                         \
    float* Bs = sm_ + 2*128*40;      /* [2][128][40] */                         \
    const int tid  = threadIdx.x;                                               \
    const int warp = tid >> 5;                                                  \
    const int wm   = warp & 3;       /* m0 = wm*32 */                           \
    const int wn   = warp >> 2;      /* n0 = wn*64 */                           \
    const int lr   = tid >> 1;       /* loader row 0..127 */                    \
    const int lc   = (tid & 1) << 4; /* 0 or 16 */                              \
    wmma::fragment<wmma::accumulator,16,16,8,float> acc[2][4];                  \
    _Pragma("unroll")                                                           \
    for (int i=0;i<2;i++)                                                       \
        _Pragma("unroll")                                                       \
        for (int j=0;j<4;j++) wmma::fill_fragment(acc[i][j], 0.0f);             \
    float a_reg[16], b_reg[16];                                                 \
    _Pragma("unroll")                                                           \
    for (int q = 0; q < 4; q++) {                                               \
        *(float4*)(a_reg+q*4) = *(const float4*)((APTR) + (size_t)(mBase+lr)*(LDA) + lc + q*4); \
        *(float4*)(b_reg+q*4) = *(const float4*)((BPTR) + (size_t)(nBase+lr)*(LDB) + lc + q*4); \
    }                                                                           \
    _Pragma("unroll")                                                           \
    for (int q = 0; q < 16; q++) {                                              \
        As[lr*40 + lc + q] = wmma::__float_to_tf32(a_reg[q]);                   \
        Bs[lr*40 + lc + q] = wmma::__float_to_tf32(b_reg[q]);                   \
    }                                                                           \
    __syncthreads();                                                            \
    int cur = 0;                                                                \
    for (int k0 = 0; k0 < (KTOT); k0 += 32) {                                   \
        const bool more = (k0 + 32) < (KTOT);                                   \
        if (more) {                                                             \
            _Pragma("unroll")                                                   \
            for (int q = 0; q < 4; q++) {                                       \
                *(float4*)(a_reg+q*4) = *(const float4*)((APTR) + (size_t)(mBase+lr)*(LDA) + k0+32 + lc + q*4); \
                *(float4*)(b_reg+q*4) = *(const float4*)((BPTR) + (size_t)(nBase+lr)*(LDB) + k0+32 + lc + q*4); \
            }                                                                   \
        }                                                                       \
        const float* Ac = As + cur*5120;                                        \
        const float* Bc = Bs + cur*5120;                                        \
        _Pragma("unroll")                                                       \
        for (int kk = 0; kk < 32; kk += 8) {                                    \
            wmma::fragment<wmma::matrix_a,16,16,8,wmma::precision::tf32,wmma::row_major> af[2]; \
            wmma::fragment<wmma::matrix_b,16,16,8,wmma::precision::tf32,wmma::col_major> bf[4]; \
            _Pragma("unroll")                                                   \
            for (int i=0;i<2;i++) wmma::load_matrix_sync(af[i], Ac + (wm*32+i*16)*40 + kk, 40); \
            _Pragma("unroll")                                                   \
            for (int j=0;j<4;j++) wmma::load_matrix_sync(bf[j], Bc + (wn*64+j*16)*40 + kk, 40); \
            _Pragma("unroll")                                                   \
            for (int i=0;i<2;i++)                                               \
                _Pragma("unroll")                                               \
                for (int j=0;j<4;j++)                                           \
                    wmma::mma_sync(acc[i][j], af[i], bf[j], acc[i][j]);         \
        }                                                                       \
        if (more) {                                                             \
            float* An = As + (cur^1)*5120;                                      \
            float* Bn = Bs + (cur^1)*5120;                                      \
            _Pragma("unroll")                                                   \
            for (int q = 0; q < 16; q++) {                                      \
                An[lr*40 + lc + q] = wmma::__float_to_tf32(a_reg[q]);           \
                Bn[lr*40 + lc + q] = wmma::__float_to_tf32(b_reg[q]);           \
            }                                                                   \
        }                                                                       \
        __syncthreads();                                                        \
        cur ^= 1;                                                               \
    }

__global__ __launch_bounds__(256) void qkv_mma_kernel(
    const float* __restrict__ x,
    const float* __restrict__ wq, const float* __restrict__ wk,
    const float* __restrict__ wv)
{
    const int which = blockIdx.z;
    const float* w = (which==0) ? wq : (which==1) ? wk : wv;
    float* outp = g_tmp + (size_t)which * M1 * E;

    const int mBase = blockIdx.y * 128, nBase = blockIdx.x * 128;
    MMA_NT_LOOP_DB(x, E, w, E, E)

    #pragma unroll
    for (int i=0;i<2;i++)
        #pragma unroll
        for (int j=0;j<4;j++)
            wmma::store_matrix_sync(
                outp + (size_t)(mBase + wm*32 + i*16)*E + nBase + wn*64 + j*16,
                acc[i][j], E, wmma::mem_row_major);
}

__global__ __launch_bounds__(256) void qkv_epi_kernel(
    const float* __restrict__ bq, const float* __restrict__ bk,
    const float* __restrict__ bv)
{
    const int which = blockIdx.z;
    const float* bias = (which==0) ? bq : (which==1) ? bk : bv;
    const float* tmp  = g_tmp + (size_t)which * M1 * E;
    float* outp       = (which==0) ? g_q : (which==1) ? g_k : g_v;
    const float scale = (which==0) ? 0.125f : 1.0f;   // HD^-0.5

    const int idx = (blockIdx.x * 256 + threadIdx.x) * 4;
    const int m = idx / E, n = idx % E;
    const int t = m >> 2, b = m & 3;          // m = t*BSZ + b
    const int h = n >> 6, d = n & 63;         // n = h*HD + d

    const float4 v4 = *(const float4*)(tmp + (size_t)m*E + n);
    const float4 b4 = *(const float4*)(bias + n);
    float4 o4;
    o4.x = (v4.x + b4.x) * scale;
    o4.y = (v4.y + b4.y) * scale;
    o4.z = (v4.z + b4.z) * scale;
    o4.w = (v4.w + b4.w) * scale;
    *(float4*)(outp + ((size_t)(b*H + h)*TGT + t)*HD + d) = o4;
}

// ============================================================
// PART 2: fused attention (stats -> fctx -> favg), no P matrix
// q-tile = 128 rows, k-tile = 128 cols, smem S 128x132 fp32
// ============================================================

// load 128x64 fp32 tile (row stride HD) -> smem ld 72, tf32-rounded
__device__ __forceinline__ void load_tile64(
    const float* __restrict__ src, float* __restrict__ dst, int tid)
{
    const int lr = tid >> 1;          // 0..127
    const int lc = (tid & 1) << 5;    // 0 or 32
    #pragma unroll
    for (int q2 = 0; q2 < 8; q2++) {
        const float4 v = *(const float4*)(src + (size_t)lr*HD + lc + q2*4);
        dst[lr*72 + lc + q2*4 + 0] = wmma::__float_to_tf32(v.x);
        dst[lr*72 + lc + q2*4 + 1] = wmma::__float_to_tf32(v.y);
        dst[lr*72 + lc + q2*4 + 2] = wmma::__float_to_tf32(v.z);
        dst[lr*72 + lc + q2*4 + 3] = wmma::__float_to_tf32(v.w);
    }
}

// S[128x128] = Q[128x64] @ K[128x64]^T -> Ss (fp32, ld 132)
__device__ __forceinline__ void mma_scores_tile(
    const float* __restrict__ Qs, const float* __restrict__ Ks,
    float* __restrict__ Ss, int wm, int wn)
{
    wmma::fragment<wmma::accumulator,16,16,8,float> s[2][4];
    #pragma unroll
    for (int i=0;i<2;i++)
        #pragma unroll
        for (int j=0;j<4;j++) wmma::fill_fragment(s[i][j], 0.0f);
    #pragma unroll
    for (int kk = 0; kk < 64; kk += 8) {
        wmma::fragment<wmma::matrix_a,16,16,8,wmma::precision::tf32,wmma::row_major> af[2];
        wmma::fragment<wmma::matrix_b,16,16,8,wmma::precision::tf32,wmma::col_major> bf[4];
        #pragma unroll
        for (int i=0;i<2;i++) wmma::load_matrix_sync(af[i], Qs + (wm*32+i*16)*72 + kk, 72);
        #pragma unroll
        for (int j=0;j<4;j++) wmma::load_matrix_sync(bf[j], Ks + (wn*64+j*16)*72 + kk, 72);
        #pragma unroll
        for (int i=0;i<2;i++)
            #pragma unroll
            for (int j=0;j<4;j++)
                wmma::mma_sync(s[i][j], af[i], bf[j], s[i][j]);
    }
    #pragma unroll
    for (int i=0;i<2;i++)
        #pragma unroll
        for (int j=0;j<4;j++)
            wmma::store_matrix_sync(Ss + (wm*32+i*16)*132 + wn*64 + j*16,
                                    s[i][j], 132, wmma::mem_row_major);
}

#define STATS_SMEM ((2*128*72 + 128*132)*4)
#define FCTX_SMEM  ((3*128*72 + 128*132)*4)
#define FAVG_SMEM  ((2*128*72 + 2*128*132)*4)

// ---- kernel A: softmax stats per (bh, q) row ----
__global__ __launch_bounds__(256) void stats_kernel()
{
    extern __shared__ float sm_[];
    float* Qs = sm_;                 // 128*72
    float* Ks = sm_ + 128*72;        // 128*72
    float* Ss = sm_ + 2*128*72;      // 128*132
    __shared__ float ms[128], ssum[128];

    const int tid = threadIdx.x, warp = tid>>5, wm = warp&3, wn = warp>>2;
    const int qt = blockIdx.x, bh = blockIdx.y;
    const float* Qg = g_q + (size_t)bh*TGT*HD + (size_t)qt*128*HD;
    const float* Kg = g_k + (size_t)bh*TGT*HD;

    load_tile64(Qg, Qs, tid);
    if (tid < 128) { ms[tid] = -INFINITY; ssum[tid] = 0.0f; }
    __syncthreads();

    const int r = tid >> 1, base = (tid & 1) << 6;   // 64-wide half-rows
    for (int kt = 0; kt < TGT/128; kt++) {
        load_tile64(Kg + (size_t)kt*128*HD, Ks, tid);
        __syncthreads();
        mma_scores_tile(Qs, Ks, Ss, wm, wn);
        __syncthreads();

        float tmax = -INFINITY;
        #pragma unroll 8
        for (int j = 0; j < 64; j++) tmax = fmaxf(tmax, Ss[r*132 + base + j]);
        tmax = fmaxf(tmax, __shfl_xor_sync(0xffffffffu, tmax, 1));
        const float mo = ms[r];
        const float mn = fmaxf(mo, tmax);
        float tsum = 0.0f;
        #pragma unroll 8
        for (int j = 0; j < 64; j++) tsum += __expf(Ss[r*132 + base + j] - mn);
        tsum += __shfl_xor_sync(0xffffffffu, tsum, 1);
        if ((tid & 1) == 0) {
            ssum[r] = ssum[r] * __expf(mo - mn) + tsum;
            ms[r]   = mn;
        }
        __syncthreads();
    }
    if (tid < 128) {
        g_m[(size_t)bh*TGT + qt*128 + tid] = ms[tid];
        g_s[(size_t)bh*TGT + qt*128 + tid] = ssum[tid];
    }
}

// ---- kernel B: ctx = softmax(S) @ V, recomputing S per tile ----
__global__ __launch_bounds__(256) void fctx_kernel()
{
    extern __shared__ float sm_[];
    float* Qs = sm_;                 // 128*72
    float* Ks = sm_ + 128*72;        // 128*72
    float* Vs = sm_ + 2*128*72;      // 128*72
    float* Ss = sm_ + 3*128*72;      // 128*132
    __shared__ float ms[128], is[128];

    const int tid = threadIdx.x, warp = tid>>5, wm = warp&3, wn = warp>>2;
    const int qt = blockIdx.x, bh = blockIdx.y;
    const int b = bh >> 4, h = bh & 15;
    const float* Qg = g_q + (size_t)bh*TGT*HD + (size_t)qt*128*HD;
    const float* Kg = g_k + (size_t)bh*TGT*HD;
    const float* Vg = g_v + (size_t)bh*TGT*HD;

    load_tile64(Qg, Qs, tid);
    if (tid < 128) {
        ms[tid] = g_m[(size_t)bh*TGT + qt*128 + tid];
        is[tid] = 1.0f / g_s[(size_t)bh*TGT + qt*128 + tid];
    }

    wmma::fragment<wmma::accumulator,16,16,8,float> cacc[2][2];
    #pragma unroll
    for (int i=0;i<2;i++)
        #pragma unroll
        for (int j=0;j<2;j++) wmma::fill_fragment(cacc[i][j], 0.0f);

    const int r = tid >> 1, base = (tid & 1) << 6;
    __syncthreads();

    for (int kt = 0; kt < TGT/128; kt++) {
        load_tile64(Kg + (size_t)kt*128*HD, Ks, tid);
        load_tile64(Vg + (size_t)kt*128*HD, Vs, tid);
        __syncthreads();
        mma_scores_tile(Qs, Ks, Ss, wm, wn);
        __syncthreads();
        // p = exp(S - m) * (1/sum), tf32-rounded in place
        const float mv = ms[r], iv = is[r];
        #pragma unroll 8
        for (int j = 0; j < 64; j++) {
            const int o = r*132 + base + j;
            Ss[o] = wmma::__float_to_tf32(__expf(Ss[o] - mv) * iv);
        }
        __syncthreads();
        // ctx += P(128x128) @ V(128x64); warp = 32x32 tile
        #pragma unroll
        for (int kk = 0; kk < 128; kk += 8) {
            wmma::fragment<wmma::matrix_a,16,16,8,wmma::precision::tf32,wmma::row_major> paf[2];
            wmma::fragment<wmma::matrix_b,16,16,8,wmma::precision::tf32,wmma::row_major> pbf[2];
            #pragma unroll
            for (int i=0;i<2;i++) wmma::load_matrix_sync(paf[i], Ss + (wm*32+i*16)*132 + kk, 132);
            #pragma unroll
            for (int j=0;j<2;j++) wmma::load_matrix_sync(pbf[j], Vs + kk*72 + wn*32 + j*16, 72);
            #pragma unroll
            for (int i=0;i<2;i++)
                #pragma unroll
                for (int j=0;j<2;j++)
                    wmma::mma_sync(cacc[i][j], paf[i], pbf[j], cacc[i][j]);
        }
        __syncthreads();
    }
    // g_ctx[(q*BSZ+b)*E + h*HD + d], row stride BSZ*E (validated pattern)
    #pragma unroll
    for (int i=0;i<2;i++)
        #pragma unroll
        for (int j=0;j<2;j++)
            wmma::store_matrix_sync(
                g_ctx + ((size_t)(qt*128 + wm*32 + i*16)*BSZ + b)*E + h*HD + wn*32 + j*16,
                cacc[i][j], BSZ*E, wmma::mem_row_major);
}

// ---- kernel C: avg over heads, recomputing S per (b, q-tile, k-tile) ----
__global__ __launch_bounds__(256) void favg_kernel(float* __restrict__ avg_out)
{
    extern __shared__ float sm_[];
    float* Qs = sm_;                 // 128*72
    float* Ks = sm_ + 128*72;        // 128*72
    float* Ss = sm_ + 2*128*72;      // 128*132
    float* Av = Ss  + 128*132;       // 128*132
    __shared__ float ms[128], is[128];

    const int tid = threadIdx.x, warp = tid>>5, wm = warp&3, wn = warp>>2;
    const int kt = blockIdx.x, qt = blockIdx.y, b = blockIdx.z;

    for (int idx = tid; idx < 128*132; idx += 256) Av[idx] = 0.0f;

    const int r = tid >> 1, base = (tid & 1) << 6;
    for (int h = 0; h < H; h++) {
        const int bh = b*H + h;
        load_tile64(g_q + (size_t)bh*TGT*HD + (size_t)qt*128*HD, Qs, tid);
        load_tile64(g_k + (size_t)bh*TGT*HD + (size_t)kt*128*HD, Ks, tid);
        if (tid < 128) {
            ms[tid] = g_m[(size_t)bh*TGT + qt*128 + tid];
            is[tid] = 1.0f / g_s[(size_t)bh*TGT + qt*128 + tid];
        }
        __syncthreads();
        mma_scores_tile(Qs, Ks, Ss, wm, wn);
        __syncthreads();
        const float mv = ms[r], iv = is[r];
        #pragma unroll 8
        for (int j = 0; j < 64; j++) {
            const int o = r*132 + base + j;
            Av[o] += __expf(Ss[o] - mv) * iv;
        }
        __syncthreads();
    }
    const float invH = 1.0f / (float)H;
    #pragma unroll
    for (int j4 = 0; j4 < 64; j4 += 4) {
        float4 a4 = *(float4*)&Av[r*132 + base + j4];
        a4.x *= invH; a4.y *= invH; a4.z *= invH; a4.w *= invH;
        *(float4*)(avg_out + ((size_t)b*TGT + qt*128 + r)*TGT + kt*128 + base + j4) = a4;
    }
}

// ============================================================
// PART 3: out projection (validated) + epilogue
// ============================================================

__global__ __launch_bounds__(256) void outproj_mma_kernel(const float* __restrict__ wo)
{
    float* outp = g_tmp;
    const int mBase = blockIdx.y * 128, nBase = blockIdx.x * 128;
    MMA_NT_LOOP_DB(g_ctx, E, wo, E, E)

    #pragma unroll
    for (int i=0;i<2;i++)
        #pragma unroll
        for (int j=0;j<4;j++)
            wmma::store_matrix_sync(
                outp + (size_t)(mBase + wm*32 + i*16)*E + nBase + wn*64 + j*16,
                acc[i][j], E, wmma::mem_row_major);
}

__global__ __launch_bounds__(256) void outproj_epi_kernel(
    const float* __restrict__ bo, float* __restrict__ out)
{
    const int idx = (blockIdx.x * 256 + threadIdx.x) * 4;
    const int n = idx % E;
    const float4 v4 = *(const float4*)(g_tmp + idx);
    const float4 b4 = *(const float4*)(bo + n);
    float4 o4;
    o4.x = v4.x + b4.x; o4.y = v4.y + b4.y;
    o4.z = v4.z + b4.z; o4.w = v4.w + b4.w;
    *(float4*)(out + idx) = o4;
}

extern "C" void kernel_launch(void* const* d_in, const int* in_sizes, int n_in,
                              void* d_out, int out_size)
{
    (void)in_sizes; (void)n_in; (void)out_size;
    const float* query = (const float*)d_in[0];
    const float* wq = (const float*)d_in[1];
    const float* bq = (const float*)d_in[2];
    const float* wk = (const float*)d_in[3];
    const float* bk = (const float*)d_in[4];
    const float* wv = (const float*)d_in[5];
    const float* bv = (const float*)d_in[6];
    const float* wo = (const float*)d_in[7];
    const float* bo = (const float*)d_in[8];

    float* out = (float*)d_out;                       // [T,B,E]
    float* avg = out + (size_t)TGT*BSZ*E;             // [B,T,T]

    // opt-in to >48KB dynamic smem (idempotent host-side attrs; no allocation)
    cudaFuncSetAttribute(qkv_mma_kernel,     cudaFuncAttributeMaxDynamicSharedMemorySize, NT_SMEM_BYTES);
    cudaFuncSetAttribute(outproj_mma_kernel, cudaFuncAttributeMaxDynamicSharedMemorySize, NT_SMEM_BYTES);
    cudaFuncSetAttribute(stats_kernel,       cudaFuncAttributeMaxDynamicSharedMemorySize, STATS_SMEM);
    cudaFuncSetAttribute(fctx_kernel,        cudaFuncAttributeMaxDynamicSharedMemorySize, FCTX_SMEM);
    cudaFuncSetAttribute(favg_kernel,        cudaFuncAttributeMaxDynamicSharedMemorySize, FAVG_SMEM);

    dim3 t256(256);
    qkv_mma_kernel<<<dim3(E/128, M1/128, 3), t256, NT_SMEM_BYTES>>>(query, wq, wk, wv);
    qkv_epi_kernel<<<dim3(M1*E/1024, 1, 3), t256>>>(bq, bk, bv);
    stats_kernel<<<dim3(TGT/128, NBH), t256, STATS_SMEM>>>();
    fctx_kernel<<<dim3(TGT/128, NBH), t256, FCTX_SMEM>>>();
    favg_kernel<<<dim3(TGT/128, TGT/128, BSZ), t256, FAVG_SMEM>>>(avg);
    outproj_mma_kernel<<<dim3(E/128, M1/128, 1), t256, NT_SMEM_BYTES>>>(wo);
    outproj_epi_kernel<<<dim3(M1*E/1024, 1, 1), t256>>>(bo, out);
}